// round 1
// baseline (speedup 1.0000x reference)
#include <cuda_runtime.h>
#include <cuda_bf16.h>

#define NUM_POINTS 16
#define IN_CHANNELS 64
#define OUT_CHANNELS 256
#define NUM_STEPS 3

__device__ __forceinline__ float iterate_g(float x, const float* __restrict__ c0,
                                           const float* __restrict__ c1) {
#pragma unroll
    for (int s = 0; s < NUM_STEPS; s++) {
        float t = tanhf(x);
        // round-half-to-even to match jnp.round
        int pos = (int)rintf((1.0f + t) * (NUM_POINTS * 0.5f));
        pos = max(0, min(NUM_POINTS - 1, pos));
        x += (c0[pos] + t * c1[pos]) * (1.0f / (float)NUM_STEPS);
    }
    return x;
}

__global__ __launch_bounds__(256) void functional_flow_kernel(
    const float* __restrict__ data,
    const float* __restrict__ angles,
    const float* __restrict__ velo,
    float* __restrict__ out,
    int nrows) {
    __shared__ float c0[NUM_POINTS];
    __shared__ float c1[NUM_POINTS];

    int tid = threadIdx.x;
    if (tid < NUM_POINTS) {
        float a = angles[tid];
        float v = velo[tid];
        c0[tid] = v * cosf(a);
        c1[tid] = v * sinf(a);
    }
    __syncthreads();

    int warp = tid >> 5;
    int lane = tid & 31;
    int row = blockIdx.x * (blockDim.x >> 5) + warp;
    if (row >= nrows) return;

    // 64 channels per row, 2 per lane, coalesced float2 load
    const float2* dp = reinterpret_cast<const float2*>(data);
    float2 d = dp[row * (IN_CHANNELS / 2) + lane];

    float s = iterate_g(d.x, c0, c1) + iterate_g(d.y, c0, c1);

    // warp-wide sum over the 64 channels
#pragma unroll
    for (int off = 16; off > 0; off >>= 1)
        s += __shfl_xor_sync(0xFFFFFFFFu, s, off);

    // broadcast the row sum to all 256 out channels: 8 floats/lane = 2x float4
    float4 v4 = make_float4(s, s, s, s);
    float4* op = reinterpret_cast<float4*>(out + (size_t)row * OUT_CHANNELS);
    op[lane * 2 + 0] = v4;
    op[lane * 2 + 1] = v4;
}

extern "C" void kernel_launch(void* const* d_in, const int* in_sizes, int n_in,
                              void* d_out, int out_size) {
    const float* data   = (const float*)d_in[0];
    const float* angles = (const float*)d_in[1];
    const float* velo   = (const float*)d_in[2];
    float* out = (float*)d_out;

    int nrows = in_sizes[0] / IN_CHANNELS;  // 4096
    int warps_per_block = 256 / 32;         // 8 rows per block
    int blocks = (nrows + warps_per_block - 1) / warps_per_block;  // 512

    functional_flow_kernel<<<blocks, 256>>>(data, angles, velo, out, nrows);
}